// round 14
// baseline (speedup 1.0000x reference)
#include <cuda_runtime.h>
#include <math.h>

// Cosine similarity per row: out[n] = dot(p[n],h[n]) / (max(||p||,eps)*max(||h||,eps))
// N = 65536 rows, D = 1024 floats (= 256 float4).
//
// Grid-stride persistent kernel, one WARP per row per iteration.
// Cross-row software pipeline: after the FMA partials consume the row buffer,
// the NEXT row's 16 loads are issued (overwriting the buffer) BEFORE the
// shuffle-reduction tail, so DRAM has loads in flight during the ~200-cycle
// reduce/sqrt/store phase that previously left the memory system idle.

#define D_DIM 1024
#define F4_PER_ROW (D_DIM / 4)        // 256
#define THREADS 256                   // 8 warps per CTA
#define WARPS_PER_CTA 8
#define NUM_CTAS 444                  // 148 SMs * 3 resident CTAs
#define EPS 1e-12f

__global__ __launch_bounds__(THREADS, 3)
void cosine_sim_persist_kernel(const float4* __restrict__ p,
                               const float4* __restrict__ h,
                               float* __restrict__ out,
                               int n_rows)
{
    const int lane = threadIdx.x & 31;
    const int gwarp = blockIdx.x * WARPS_PER_CTA + (threadIdx.x >> 5);
    const int total_warps = gridDim.x * WARPS_PER_CTA;

    long long row = gwarp;
    if (row >= n_rows) return;

    const long long stride_f4 = (long long)total_warps * F4_PER_ROW;
    const float4* __restrict__ prow = p + row * F4_PER_ROW + lane;
    const float4* __restrict__ hrow = h + row * F4_PER_ROW + lane;

    // Prologue: load first row (16 independent LDG.128, streaming).
    float4 pv[8], hv[8];
    #pragma unroll
    for (int i = 0; i < 8; i++) pv[i] = __ldcs(prow + i * 32);
    #pragma unroll
    for (int i = 0; i < 8; i++) hv[i] = __ldcs(hrow + i * 32);

    while (true) {
        const long long next = row + total_warps;

        // 1) Consume the buffer into three scalar partials.
        float dot = 0.0f, pp = 0.0f, hh = 0.0f;
        #pragma unroll
        for (int i = 0; i < 8; i++) {
            dot = fmaf(pv[i].x, hv[i].x, dot);
            dot = fmaf(pv[i].y, hv[i].y, dot);
            dot = fmaf(pv[i].z, hv[i].z, dot);
            dot = fmaf(pv[i].w, hv[i].w, dot);
            pp  = fmaf(pv[i].x, pv[i].x, pp);
            pp  = fmaf(pv[i].y, pv[i].y, pp);
            pp  = fmaf(pv[i].z, pv[i].z, pp);
            pp  = fmaf(pv[i].w, pv[i].w, pp);
            hh  = fmaf(hv[i].x, hv[i].x, hh);
            hh  = fmaf(hv[i].y, hv[i].y, hh);
            hh  = fmaf(hv[i].z, hv[i].z, hh);
            hh  = fmaf(hv[i].w, hv[i].w, hh);
        }

        // 2) Issue NEXT row's loads now — they fly during the reduction tail.
        const bool have_next = (next < n_rows);
        if (have_next) {
            prow += stride_f4;
            hrow += stride_f4;
            #pragma unroll
            for (int i = 0; i < 8; i++) pv[i] = __ldcs(prow + i * 32);
            #pragma unroll
            for (int i = 0; i < 8; i++) hv[i] = __ldcs(hrow + i * 32);
        }

        // 3) Shuffle-reduce the partials (independent of the in-flight loads).
        #pragma unroll
        for (int offset = 16; offset > 0; offset >>= 1) {
            dot += __shfl_xor_sync(0xFFFFFFFFu, dot, offset);
            pp  += __shfl_xor_sync(0xFFFFFFFFu, pp,  offset);
            hh  += __shfl_xor_sync(0xFFFFFFFFu, hh,  offset);
        }

        if (lane == 0) {
            float pn = fmaxf(sqrtf(pp), EPS);
            float hn = fmaxf(sqrtf(hh), EPS);
            out[row] = dot / (pn * hn);
        }

        if (!have_next) break;
        row = next;
    }
}

extern "C" void kernel_launch(void* const* d_in, const int* in_sizes, int n_in,
                              void* d_out, int out_size) {
    const float4* p = (const float4*)d_in[0];
    const float4* h = (const float4*)d_in[1];
    float* out = (float*)d_out;

    const int n_rows = in_sizes[0] / D_DIM;          // 65536
    cosine_sim_persist_kernel<<<NUM_CTAS, THREADS>>>(p, h, out, n_rows);
}

// round 15
// speedup vs baseline: 1.0034x; 1.0034x over previous
#include <cuda_runtime.h>
#include <math.h>

// Cosine similarity per row: out[n] = dot(p[n],h[n]) / (max(||p||,eps)*max(||h||,eps))
// N = 65536 rows, D = 1024 floats (= 256 float4).
//
// Grid-stride persistent kernel, one WARP per row per iteration.
// Cross-row software pipeline: after the FMA partials consume the row buffer,
// the NEXT row's 16 loads are issued (overwriting the buffer) BEFORE the
// shuffle-reduction tail, so DRAM has loads in flight during the ~200-cycle
// reduce/sqrt/store phase that previously left the memory system idle.

#define D_DIM 1024
#define F4_PER_ROW (D_DIM / 4)        // 256
#define THREADS 256                   // 8 warps per CTA
#define WARPS_PER_CTA 8
#define NUM_CTAS 444                  // 148 SMs * 3 resident CTAs
#define EPS 1e-12f

__global__ __launch_bounds__(THREADS, 3)
void cosine_sim_persist_kernel(const float4* __restrict__ p,
                               const float4* __restrict__ h,
                               float* __restrict__ out,
                               int n_rows)
{
    const int lane = threadIdx.x & 31;
    const int gwarp = blockIdx.x * WARPS_PER_CTA + (threadIdx.x >> 5);
    const int total_warps = gridDim.x * WARPS_PER_CTA;

    long long row = gwarp;
    if (row >= n_rows) return;

    const long long stride_f4 = (long long)total_warps * F4_PER_ROW;
    const float4* __restrict__ prow = p + row * F4_PER_ROW + lane;
    const float4* __restrict__ hrow = h + row * F4_PER_ROW + lane;

    // Prologue: load first row (16 independent LDG.128, streaming).
    float4 pv[8], hv[8];
    #pragma unroll
    for (int i = 0; i < 8; i++) pv[i] = __ldcs(prow + i * 32);
    #pragma unroll
    for (int i = 0; i < 8; i++) hv[i] = __ldcs(hrow + i * 32);

    while (true) {
        const long long next = row + total_warps;

        // 1) Consume the buffer into three scalar partials.
        float dot = 0.0f, pp = 0.0f, hh = 0.0f;
        #pragma unroll
        for (int i = 0; i < 8; i++) {
            dot = fmaf(pv[i].x, hv[i].x, dot);
            dot = fmaf(pv[i].y, hv[i].y, dot);
            dot = fmaf(pv[i].z, hv[i].z, dot);
            dot = fmaf(pv[i].w, hv[i].w, dot);
            pp  = fmaf(pv[i].x, pv[i].x, pp);
            pp  = fmaf(pv[i].y, pv[i].y, pp);
            pp  = fmaf(pv[i].z, pv[i].z, pp);
            pp  = fmaf(pv[i].w, pv[i].w, pp);
            hh  = fmaf(hv[i].x, hv[i].x, hh);
            hh  = fmaf(hv[i].y, hv[i].y, hh);
            hh  = fmaf(hv[i].z, hv[i].z, hh);
            hh  = fmaf(hv[i].w, hv[i].w, hh);
        }

        // 2) Issue NEXT row's loads now — they fly during the reduction tail.
        const bool have_next = (next < n_rows);
        if (have_next) {
            prow += stride_f4;
            hrow += stride_f4;
            #pragma unroll
            for (int i = 0; i < 8; i++) pv[i] = __ldcs(prow + i * 32);
            #pragma unroll
            for (int i = 0; i < 8; i++) hv[i] = __ldcs(hrow + i * 32);
        }

        // 3) Shuffle-reduce the partials (independent of the in-flight loads).
        #pragma unroll
        for (int offset = 16; offset > 0; offset >>= 1) {
            dot += __shfl_xor_sync(0xFFFFFFFFu, dot, offset);
            pp  += __shfl_xor_sync(0xFFFFFFFFu, pp,  offset);
            hh  += __shfl_xor_sync(0xFFFFFFFFu, hh,  offset);
        }

        if (lane == 0) {
            float pn = fmaxf(sqrtf(pp), EPS);
            float hn = fmaxf(sqrtf(hh), EPS);
            out[row] = dot / (pn * hn);
        }

        if (!have_next) break;
        row = next;
    }
}

extern "C" void kernel_launch(void* const* d_in, const int* in_sizes, int n_in,
                              void* d_out, int out_size) {
    const float4* p = (const float4*)d_in[0];
    const float4* h = (const float4*)d_in[1];
    float* out = (float*)d_out;

    const int n_rows = in_sizes[0] / D_DIM;          // 65536
    cosine_sim_persist_kernel<<<NUM_CTAS, THREADS>>>(p, h, out, n_rows);
}

// round 17
// speedup vs baseline: 1.0146x; 1.0112x over previous
#include <cuda_runtime.h>
#include <math.h>

// Cosine similarity per row: out[n] = dot(p[n],h[n]) / (max(||p||,eps)*max(||h||,eps))
// N = 65536 rows, D = 1024 floats (= 256 float4).
//
// Grid-stride persistent kernel, one WARP per row per iteration.
// Cross-row software pipeline: after the FMA partials consume the row buffer,
// the NEXT row's 16 loads are issued (overwriting the buffer) BEFORE the
// shuffle-reduction tail, so DRAM has loads in flight during the ~200-cycle
// reduce/sqrt/store phase that previously left the memory system idle.

#define D_DIM 1024
#define F4_PER_ROW (D_DIM / 4)        // 256
#define THREADS 256                   // 8 warps per CTA
#define WARPS_PER_CTA 8
#define NUM_CTAS 444                  // 148 SMs * 3 resident CTAs
#define EPS 1e-12f

__global__ __launch_bounds__(THREADS, 3)
void cosine_sim_persist_kernel(const float4* __restrict__ p,
                               const float4* __restrict__ h,
                               float* __restrict__ out,
                               int n_rows)
{
    const int lane = threadIdx.x & 31;
    const int gwarp = blockIdx.x * WARPS_PER_CTA + (threadIdx.x >> 5);
    const int total_warps = gridDim.x * WARPS_PER_CTA;

    long long row = gwarp;
    if (row >= n_rows) return;

    const long long stride_f4 = (long long)total_warps * F4_PER_ROW;
    const float4* __restrict__ prow = p + row * F4_PER_ROW + lane;
    const float4* __restrict__ hrow = h + row * F4_PER_ROW + lane;

    // Prologue: load first row (16 independent LDG.128, streaming).
    float4 pv[8], hv[8];
    #pragma unroll
    for (int i = 0; i < 8; i++) pv[i] = __ldcs(prow + i * 32);
    #pragma unroll
    for (int i = 0; i < 8; i++) hv[i] = __ldcs(hrow + i * 32);

    while (true) {
        const long long next = row + total_warps;

        // 1) Consume the buffer into three scalar partials.
        float dot = 0.0f, pp = 0.0f, hh = 0.0f;
        #pragma unroll
        for (int i = 0; i < 8; i++) {
            dot = fmaf(pv[i].x, hv[i].x, dot);
            dot = fmaf(pv[i].y, hv[i].y, dot);
            dot = fmaf(pv[i].z, hv[i].z, dot);
            dot = fmaf(pv[i].w, hv[i].w, dot);
            pp  = fmaf(pv[i].x, pv[i].x, pp);
            pp  = fmaf(pv[i].y, pv[i].y, pp);
            pp  = fmaf(pv[i].z, pv[i].z, pp);
            pp  = fmaf(pv[i].w, pv[i].w, pp);
            hh  = fmaf(hv[i].x, hv[i].x, hh);
            hh  = fmaf(hv[i].y, hv[i].y, hh);
            hh  = fmaf(hv[i].z, hv[i].z, hh);
            hh  = fmaf(hv[i].w, hv[i].w, hh);
        }

        // 2) Issue NEXT row's loads now — they fly during the reduction tail.
        const bool have_next = (next < n_rows);
        if (have_next) {
            prow += stride_f4;
            hrow += stride_f4;
            #pragma unroll
            for (int i = 0; i < 8; i++) pv[i] = __ldcs(prow + i * 32);
            #pragma unroll
            for (int i = 0; i < 8; i++) hv[i] = __ldcs(hrow + i * 32);
        }

        // 3) Shuffle-reduce the partials (independent of the in-flight loads).
        #pragma unroll
        for (int offset = 16; offset > 0; offset >>= 1) {
            dot += __shfl_xor_sync(0xFFFFFFFFu, dot, offset);
            pp  += __shfl_xor_sync(0xFFFFFFFFu, pp,  offset);
            hh  += __shfl_xor_sync(0xFFFFFFFFu, hh,  offset);
        }

        if (lane == 0) {
            float pn = fmaxf(sqrtf(pp), EPS);
            float hn = fmaxf(sqrtf(hh), EPS);
            out[row] = dot / (pn * hn);
        }

        if (!have_next) break;
        row = next;
    }
}

extern "C" void kernel_launch(void* const* d_in, const int* in_sizes, int n_in,
                              void* d_out, int out_size) {
    const float4* p = (const float4*)d_in[0];
    const float4* h = (const float4*)d_in[1];
    float* out = (float*)d_out;

    const int n_rows = in_sizes[0] / D_DIM;          // 65536
    cosine_sim_persist_kernel<<<NUM_CTAS, THREADS>>>(p, h, out, n_rows);
}